// round 15
// baseline (speedup 1.0000x reference)
#include <cuda_runtime.h>
#include <stdint.h>
#include <math.h>

#define BB 64
#define SS 100
#define DIN 256
#define HH 512
#define DOUT 256
#define WR 16
#define WIN 33
#define NBS (BB*SS)
#define STILE 10

// ---------------- scratch ----------------
__device__ float g_x  [NBS*DIN];   // x tf32-rounded
__device__ float g_w0 [HH*DIN];    // W0^T [N,K] tf32-rounded
__device__ float g_wq [HH*HH];
__device__ float g_wk [HH*HH];
__device__ float g_wv [HH*HH];
__device__ float g_w1 [DOUT*HH];
__device__ float g_h  [NBS*HH];
__device__ float g_q  [NBS*HH];
__device__ float g_k  [NBS*HH];
__device__ float g_v  [NBS*HH];
__device__ float g_G  [BB*SS*SS];
__device__ float g_att[NBS*HH];

__device__ __forceinline__ unsigned f2tf(float x){
    unsigned r; asm("cvt.rna.tf32.f32 %0, %1;" : "=r"(r) : "f"(x)); return r;
}
__device__ __forceinline__ float roundtf(float x){
    return __uint_as_float(f2tf(x));
}
__device__ __forceinline__ void mma_tf32(float c[4], unsigned a0,unsigned a1,unsigned a2,unsigned a3,
                                         unsigned b0, unsigned b1){
    asm volatile("mma.sync.aligned.m16n8k8.row.col.f32.tf32.tf32.f32 "
        "{%0,%1,%2,%3},{%4,%5,%6,%7},{%8,%9},{%0,%1,%2,%3};"
        : "+f"(c[0]),"+f"(c[1]),"+f"(c[2]),"+f"(c[3])
        : "r"(a0),"r"(a1),"r"(a2),"r"(a3),"r"(b0),"r"(b1));
}
__device__ __forceinline__ void ldsm4(unsigned &r0, unsigned &r1, unsigned &r2, unsigned &r3,
                                      uint32_t addr){
    asm volatile("ldmatrix.sync.aligned.m8n8.x4.shared.b16 {%0,%1,%2,%3}, [%4];"
        : "=r"(r0),"=r"(r1),"=r"(r2),"=r"(r3) : "r"(addr));
}
__device__ __forceinline__ uint32_t smem_u32(const void* p){
    uint32_t a;
    asm("{ .reg .u64 t; cvta.to.shared.u64 t, %1; cvt.u32.u64 %0, t; }" : "=r"(a) : "l"(p));
    return a;
}
__device__ __forceinline__ void cp16(void* dst, const void* src){
    uint32_t d = smem_u32(dst);
    asm volatile("cp.async.ca.shared.global [%0], [%1], 16;" :: "r"(d), "l"(src));
}
#define CP_COMMIT() asm volatile("cp.async.commit_group;" ::: "memory")
#define CP_WAIT(n)  asm volatile("cp.async.wait_group %0;" :: "n"(n) : "memory")

// ---------------- fused prepass: round x + transpose/round weights ----------------
// blocks [0,1600): x rounding. blocks [1600, 2624): weight transpose tiles.
__global__ __launch_bounds__(256)
void prepass_kernel(const float* __restrict__ x, float* __restrict__ xr,
                    const float* __restrict__ W0, const float* __restrict__ Wq,
                    const float* __restrict__ Wk, const float* __restrict__ Wv,
                    const float* __restrict__ W1,
                    float* __restrict__ tW0, float* __restrict__ tWq,
                    float* __restrict__ tWk, float* __restrict__ tWv,
                    float* __restrict__ tW1)
{
    __shared__ float ts[32][33];
    int bid = blockIdx.x;
    int tid = threadIdx.x;
    if (bid < 1600) {             // x: 409600 floats = 102400 float4
        int i = bid * 256 + tid;
        float4 v = ((const float4*)x)[i];
        v.x = roundtf(v.x); v.y = roundtf(v.y);
        v.z = roundtf(v.z); v.w = roundtf(v.w);
        ((float4*)xr)[i] = v;
        return;
    }
    int wb = bid - 1600;
    const float* W; float* T; int K, N, tile;
    if      (wb < 128) { W = W0; T = tW0; K = DIN; N = HH;   tile = wb; }
    else if (wb < 384) { W = Wq; T = tWq; K = HH;  N = HH;   tile = wb - 128; }
    else if (wb < 640) { W = Wk; T = tWk; K = HH;  N = HH;   tile = wb - 384; }
    else if (wb < 896) { W = Wv; T = tWv; K = HH;  N = HH;   tile = wb - 640; }
    else               { W = W1; T = tW1; K = HH;  N = DOUT; tile = wb - 896; }
    int ntiles_n = N >> 5;
    int k0 = (tile / ntiles_n) << 5;
    int n0 = (tile % ntiles_n) << 5;
    #pragma unroll
    for (int it = 0; it < 4; it++) {
        int idx = tid + it*256;
        int r = idx >> 5, c = idx & 31;
        ts[r][c] = W[(size_t)(k0 + r) * N + n0 + c];
    }
    __syncthreads();
    #pragma unroll
    for (int it = 0; it < 4; it++) {
        int idx = tid + it*256;
        int r = idx >> 5, c = idx & 31;       // r = n-local, c = k-local
        T[(size_t)(n0 + r) * K + k0 + c] = roundtf(ts[c][r]);
    }
}

// ---------------- tf32 GEMM core: 2-stage cp.async + ldmatrix, warp tile 64x32 (R10) ----------------
#define SA 36
#define SB 36
#define AS_STG (128*SA)
#define BS_STG (128*SB)
#define SMEM_GEMM ((2*AS_STG + 2*BS_STG) * 4)   // 73728 bytes

template<bool RELU, bool BIAS, bool ROUND>
__device__ __forceinline__
void gemm_core(const float* __restrict__ A, const float* __restrict__ Bt,
               const float* __restrict__ bias, float* __restrict__ C,
               int N, int K, int bm, int bn, float* smem)
{
    const int BK = 32;
    int tid = threadIdx.x, lane = tid & 31, w = tid >> 5;
    int wm = w >> 2, wn = w & 3;          // 2(M) x 4(N)
    int g = lane >> 2, t = lane & 3;
    int NK = K / BK;

    int a_row = wm*64 + (lane & 15);
    int a_col = (lane >> 4) * 4;
    int b_row = wn*32 + (lane & 7) + ((lane >> 4) << 3);
    int b_col = ((lane >> 3) & 1) * 4;

    uint32_t smem_base = smem_u32(smem);

    float acc[4][4][4] = {};

    #define ISSUE(kt) {                                                        \
        float* Asd = smem + ((kt)&1)*AS_STG;                                   \
        float* Bsd = smem + 2*AS_STG + ((kt)&1)*BS_STG;                        \
        int k0 = (kt)*BK;                                                      \
        _Pragma("unroll")                                                      \
        for (int i = 0; i < 4; i++) {                                          \
            int f = tid + i*256; int row = f>>3, c4 = f&7;                     \
            cp16(&Asd[row*SA + c4*4], &A[(size_t)(bm+row)*K + k0 + c4*4]);     \
        }                                                                      \
        _Pragma("unroll")                                                      \
        for (int i = 0; i < 4; i++) {                                          \
            int f = tid + i*256; int n = f>>3, c4 = f&7;                       \
            cp16(&Bsd[n*SB + c4*4], &Bt[(size_t)(bn+n)*K + k0 + c4*4]);        \
        }                                                                      \
        CP_COMMIT();                                                           \
    }

    ISSUE(0);
    for (int kt = 0; kt < NK; kt++) {
        if (kt + 1 < NK) { ISSUE(kt+1); CP_WAIT(1); }
        else             { CP_WAIT(0); }
        __syncthreads();
        uint32_t Asb = smem_base + ((kt&1)*AS_STG)*4;
        uint32_t Bsb = smem_base + (2*AS_STG + (kt&1)*BS_STG)*4;
        uint32_t aab = Asb + (a_row*SA + a_col)*4;
        uint32_t bab = Bsb + (b_row*SB + b_col)*4;
        #pragma unroll
        for (int ks = 0; ks < 4; ks++) {
            unsigned a[4][4], b[4][2];
            #pragma unroll
            for (int mt = 0; mt < 4; mt++)
                ldsm4(a[mt][0], a[mt][1], a[mt][2], a[mt][3],
                      aab + mt*(16*SA*4) + ks*32);
            ldsm4(b[0][0], b[0][1], b[1][0], b[1][1], bab + ks*32);
            ldsm4(b[2][0], b[2][1], b[3][0], b[3][1], bab + 16*SB*4 + ks*32);
            #pragma unroll
            for (int mt = 0; mt < 4; mt++)
                #pragma unroll
                for (int nt = 0; nt < 4; nt++)
                    mma_tf32(acc[mt][nt], a[mt][0],a[mt][1],a[mt][2],a[mt][3],
                             b[nt][0], b[nt][1]);
        }
        __syncthreads();
    }
    #undef ISSUE

    #pragma unroll
    for (int mt = 0; mt < 4; mt++) {
        int r0 = bm + wm*64 + mt*16 + g;
        #pragma unroll
        for (int nt = 0; nt < 4; nt++) {
            int col = bn + wn*32 + nt*8 + 2*t;
            float bx = 0.f, by = 0.f;
            if (BIAS) { bx = bias[col]; by = bias[col+1]; }
            float2 o0, o1;
            o0.x = acc[mt][nt][0] + bx; o0.y = acc[mt][nt][1] + by;
            o1.x = acc[mt][nt][2] + bx; o1.y = acc[mt][nt][3] + by;
            if (RELU) {
                o0.x=fmaxf(o0.x,0.f); o0.y=fmaxf(o0.y,0.f);
                o1.x=fmaxf(o1.x,0.f); o1.y=fmaxf(o1.y,0.f);
            }
            if (ROUND) {
                o0.x=roundtf(o0.x); o0.y=roundtf(o0.y);
                o1.x=roundtf(o1.x); o1.y=roundtf(o1.y);
            }
            *(float2*)&C[(size_t)r0*N + col]     = o0;
            *(float2*)&C[(size_t)(r0+8)*N + col] = o1;
        }
    }
}

template<bool RELU, bool BIAS, bool ROUND>
__global__ __launch_bounds__(256)
void tgemm_kernel(const float* __restrict__ A, const float* __restrict__ Bt,
                  const float* __restrict__ bias, float* __restrict__ C,
                  int N, int K)
{
    extern __shared__ float smem[];
    gemm_core<RELU, BIAS, ROUND>(A, Bt, bias, C, N, K,
                                 blockIdx.y * 128, blockIdx.x * 128, smem);
}

// Fused QKV: grid (12, 50).
__global__ __launch_bounds__(256)
void tgemm_qkv_kernel(const float* __restrict__ h,
                      const float* __restrict__ wq, const float* __restrict__ wk,
                      const float* __restrict__ wv,
                      float* __restrict__ q, float* __restrict__ k, float* __restrict__ v)
{
    extern __shared__ float smem[];
    int sel = blockIdx.x >> 2;
    const float* B = (sel == 0) ? wq : (sel == 1) ? wk : wv;
    float*       C = (sel == 0) ? q  : (sel == 1) ? k  : v;
    gemm_core<false, false, false>(h, B, nullptr, C, HH, HH,
                                   blockIdx.y * 128, (blockIdx.x & 3) * 128, smem);
}

// ---------------- per-batch Gram, grid (2, 64) — R10 version ----------------
__global__ __launch_bounds__(256)
void gram_kernel(const float* __restrict__ q, const float* __restrict__ kmat,
                 float* __restrict__ G)
{
    const int GSA=36, GSB=36, BK=32;
    __shared__ unsigned As[128*GSA];
    __shared__ unsigned Bs[64*GSB];
    int b = blockIdx.y;
    int n0 = blockIdx.x * 64;
    int tid = threadIdx.x, lane = tid & 31, w = tid >> 5;
    int wm = w & 3, wn = w >> 2;
    int g = lane >> 2, t = lane & 3;
    const float* qbp = q    + (size_t)b*SS*HH;
    const float* kbp = kmat + (size_t)b*SS*HH;

    float4 ar[4], br[2];
    float acc[2][4][4] = {};
    const int NK = HH / BK;

    #define LOADG(k0) {                                                        \
        _Pragma("unroll")                                                      \
        for (int i = 0; i < 4; i++) {                                          \
            int f = tid + i*256; int row = f>>3, c4 = (f&7)*4;                 \
            int sr = row < SS ? row : SS-1;                                    \
            ar[i] = *(const float4*)&qbp[(size_t)sr*HH + (k0) + c4];           \
        }                                                                      \
        _Pragma("unroll")                                                      \
        for (int i = 0; i < 2; i++) {                                          \
            int f = tid + i*256; int u = f>>3, c4 = (f&7)*4;                   \
            int su = (n0+u) < SS ? (n0+u) : SS-1;                              \
            br[i] = *(const float4*)&kbp[(size_t)su*HH + (k0) + c4];           \
        }                                                                      \
    }
    #define STORES() {                                                         \
        _Pragma("unroll")                                                      \
        for (int i = 0; i < 4; i++) {                                          \
            int f = tid + i*256; int row = f>>3, c4 = (f&7)*4;                 \
            int base = (c4>>3)*8 + (((c4&7)==4) ? 1 : 0);                      \
            unsigned* d = &As[row*GSA + base];                                 \
            d[0]=f2tf(ar[i].x); d[2]=f2tf(ar[i].y);                            \
            d[4]=f2tf(ar[i].z); d[6]=f2tf(ar[i].w);                            \
        }                                                                      \
        _Pragma("unroll")                                                      \
        for (int i = 0; i < 2; i++) {                                          \
            int f = tid + i*256; int u = f>>3, c4 = (f&7)*4;                   \
            int base = (c4>>3)*8 + (((c4&7)==4) ? 1 : 0);                      \
            unsigned* d = &Bs[u*GSB + base];                                   \
            d[0]=f2tf(br[i].x); d[2]=f2tf(br[i].y);                            \
            d[4]=f2tf(br[i].z); d[6]=f2tf(br[i].w);                            \
        }                                                                      \
    }

    LOADG(0); STORES(); __syncthreads();

    for (int kt = 0; kt < NK; kt++) {
        if (kt + 1 < NK) LOADG((kt+1)*BK);
        #pragma unroll
        for (int ks = 0; ks < 4; ks++) {
            unsigned a[2][4], bfr[4][2];
            #pragma unroll
            for (int mt = 0; mt < 2; mt++) {
                int r = wm*32 + mt*16 + g;
                uint2 lo = *(const uint2*)&As[r*GSA + ks*8 + 2*t];
                uint2 hi = *(const uint2*)&As[(r+8)*GSA + ks*8 + 2*t];
                a[mt][0]=lo.x; a[mt][1]=hi.x; a[mt][2]=lo.y; a[mt][3]=hi.y;
            }
            #pragma unroll
            for (int nt = 0; nt < 4; nt++) {
                int n = wn*32 + nt*8 + g;
                uint2 bb = *(const uint2*)&Bs[n*GSB + ks*8 + 2*t];
                bfr[nt][0]=bb.x; bfr[nt][1]=bb.y;
            }
            #pragma unroll
            for (int mt = 0; mt < 2; mt++)
                #pragma unroll
                for (int nt = 0; nt < 4; nt++)
                    mma_tf32(acc[mt][nt], a[mt][0],a[mt][1],a[mt][2],a[mt][3],
                             bfr[nt][0], bfr[nt][1]);
        }
        __syncthreads();
        if (kt + 1 < NK) { STORES(); __syncthreads(); }
    }
    #undef LOADG
    #undef STORES

    const float invs = 0.044194173824159216f;  // 1/sqrt(512)
    float* Gb = G + (size_t)b*SS*SS;
    #pragma unroll
    for (int mt = 0; mt < 2; mt++) {
        int r0 = wm*32 + mt*16 + g;
        #pragma unroll
        for (int nt = 0; nt < 4; nt++) {
            int col = n0 + wn*32 + nt*8 + 2*t;
            if (col + 1 < SS) {
                if (r0 < SS) {
                    Gb[r0*SS + col]     = acc[mt][nt][0]*invs;
                    Gb[r0*SS + col + 1] = acc[mt][nt][1]*invs;
                }
                if (r0 + 8 < SS) {
                    Gb[(r0+8)*SS + col]     = acc[mt][nt][2]*invs;
                    Gb[(r0+8)*SS + col + 1] = acc[mt][nt][3]*invs;
                }
            } else if (col < SS) {
                if (r0 < SS)     Gb[r0*SS + col]     = acc[mt][nt][0]*invs;
                if (r0 + 8 < SS) Gb[(r0+8)*SS + col] = acc[mt][nt][2]*invs;
            }
        }
    }
}

// ---------------- softmax + beta + weighted V (STILE=10) ----------------
__global__ __launch_bounds__(256)
void attn_kernel(const float* __restrict__ G, const float* __restrict__ v,
                 float* __restrict__ alpha_out, float* __restrict__ att)
{
    int blk = blockIdx.x;
    int b  = blk / (SS / STILE);
    int s0 = (blk % (SS / STILE)) * STILE;
    __shared__ float dmat[STILE][WIN * WIN];
    __shared__ float beta[STILE][WIN];
    const float* Gb = G + (size_t)b*SS*SS;
    int tid = threadIdx.x;

    for (int idx = tid; idx < STILE*WIN*WIN; idx += 256) {
        int si = idx / (WIN*WIN), r = idx % (WIN*WIN);
        int w_ = r / WIN, u = r % WIN;
        int s = s0 + si;
        int p  = s + WR - w_;
        int pu = s + WR - u;
        float val = 0.f;
        if (p >= 0 && p < SS && pu >= 0 && pu < SS)
            val = Gb[p*SS + pu];
        dmat[si][r] = val;
    }
    __syncthreads();

    int warp = tid >> 5, lane = tid & 31;
    for (int rr = warp; rr < STILE*WIN; rr += 8) {
        int si = rr / WIN, r = rr % WIN;
        float* row = &dmat[si][r*WIN];
        float x0 = row[lane];
        float x1 = (lane == 0) ? row[32] : -1e30f;
        float m = fmaxf(x0, x1);
#pragma unroll
        for (int o = 16; o; o >>= 1)
            m = fmaxf(m, __shfl_xor_sync(0xffffffffu, m, o));
        float e0 = __expf(x0 - m);
        float e1 = (lane == 0) ? __expf(x1 - m) : 0.f;
        float ssum = e0 + e1;
#pragma unroll
        for (int o = 16; o; o >>= 1)
            ssum += __shfl_xor_sync(0xffffffffu, ssum, o);
        float rinv = __frcp_rn(ssum);
        e0 *= rinv; e1 *= rinv;
        row[lane] = e0;
        if (lane == 0) row[32] = e1;
        float* ao = alpha_out + (size_t)(b*SS + s0 + si)*(WIN*WIN) + r*WIN;
        ao[lane] = e0;
        if (lane == 0) ao[32] = e1;
    }
    __syncthreads();

    for (int idx = tid; idx < STILE*WIN; idx += 256) {
        int si = idx / WIN, u = idx % WIN;
        float acc = 0.f;
        for (int r = 0; r < WIN; r++) acc += dmat[si][r*WIN + u];
        beta[si][u] = acc;
    }
    __syncthreads();

    int h2 = tid * 2;
    float2 acc[STILE];
#pragma unroll
    for (int si = 0; si < STILE; si++) { acc[si].x = 0.f; acc[si].y = 0.f; }

#pragma unroll
    for (int j = 0; j < STILE - 1 + 2*WR + 1; j++) {   // 42 window positions
        int p = s0 - WR + j;
        if (p >= 0 && p < SS) {
            float2 vr = *(const float2*)&v[(size_t)(b*SS + p)*HH + h2];
#pragma unroll
            for (int si = 0; si < STILE; si++) {
                int u = si + 2*WR - j;
                if (u >= 0 && u < WIN) {
                    float bu = beta[si][u];
                    acc[si].x = fmaf(bu, vr.x, acc[si].x);
                    acc[si].y = fmaf(bu, vr.y, acc[si].y);
                }
            }
        }
    }
#pragma unroll
    for (int si = 0; si < STILE; si++) {
        float2 o;
        o.x = roundtf(acc[si].x);
        o.y = roundtf(acc[si].y);
        *(float2*)&att[(size_t)(b*SS + s0 + si)*HH + h2] = o;
    }
}

// ---------------- launch ----------------
extern "C" void kernel_launch(void* const* d_in, const int* in_sizes, int n_in,
                              void* d_out, int out_size)
{
    const float* x  = (const float*)d_in[0];
    const float* W0 = (const float*)d_in[1];
    const float* b0 = (const float*)d_in[2];
    const float* Wq = (const float*)d_in[3];
    const float* Wk = (const float*)d_in[4];
    const float* Wv = (const float*)d_in[5];
    const float* W1 = (const float*)d_in[6];
    const float* b1 = (const float*)d_in[7];
    float* out = (float*)d_out;
    float* y_out     = out;
    float* alpha_out = out + (size_t)NBS * DOUT;

    float *xr,*w0t,*wqt,*wkt,*wvt,*w1t,*h,*q,*k,*v,*G,*att;
    cudaGetSymbolAddress((void**)&xr,  g_x);
    cudaGetSymbolAddress((void**)&w0t, g_w0);
    cudaGetSymbolAddress((void**)&wqt, g_wq);
    cudaGetSymbolAddress((void**)&wkt, g_wk);
    cudaGetSymbolAddress((void**)&wvt, g_wv);
    cudaGetSymbolAddress((void**)&w1t, g_w1);
    cudaGetSymbolAddress((void**)&h,   g_h);
    cudaGetSymbolAddress((void**)&q,   g_q);
    cudaGetSymbolAddress((void**)&k,   g_k);
    cudaGetSymbolAddress((void**)&v,   g_v);
    cudaGetSymbolAddress((void**)&G,   g_G);
    cudaGetSymbolAddress((void**)&att, g_att);

    cudaFuncSetAttribute(tgemm_kernel<true, true, true >, cudaFuncAttributeMaxDynamicSharedMemorySize, SMEM_GEMM);
    cudaFuncSetAttribute(tgemm_kernel<true, true, false>, cudaFuncAttributeMaxDynamicSharedMemorySize, SMEM_GEMM);
    cudaFuncSetAttribute(tgemm_qkv_kernel, cudaFuncAttributeMaxDynamicSharedMemorySize, SMEM_GEMM);

    // fused prepass: x round (1600 blocks) + weight transpose (1024 blocks)
    prepass_kernel<<<2624, 256>>>(x, xr, W0, Wq, Wk, Wv, W1,
                                  w0t, wqt, wkt, wvt, w1t);

    // h = relu(x@W0 + b0), tf32-rounded
    tgemm_kernel<true, true, true><<<dim3(HH/128, NBS/128), 256, SMEM_GEMM>>>(
        xr, w0t, b0, h, HH, DIN);
    // fused q,k,v
    tgemm_qkv_kernel<<<dim3(12, NBS/128), 256, SMEM_GEMM>>>(h, wqt, wkt, wvt, q, k, v);
    // Gram (R10 version): grid (2, 64)
    gram_kernel<<<dim3(2, BB), 256>>>(q, k, G);
    // softmax + alpha + weighted V (STILE=10)
    attn_kernel<<<NBS/STILE, 256>>>(G, v, alpha_out, att);
    // y = relu(att@W1 + b1)
    tgemm_kernel<true, true, false><<<dim3(DOUT/128, NBS/128), 256, SMEM_GEMM>>>(
        att, w1t, b1, y_out, DOUT, HH);
}

// round 16
// speedup vs baseline: 1.0766x; 1.0766x over previous
#include <cuda_runtime.h>
#include <stdint.h>
#include <math.h>

#define BB 64
#define SS 100
#define DIN 256
#define HH 512
#define DOUT 256
#define WR 16
#define WIN 33
#define NBS (BB*SS)
#define STILE 4

// ---------------- scratch ----------------
__device__ float g_x  [NBS*DIN];   // x tf32-rounded
__device__ float g_w0 [HH*DIN];    // W0^T [N,K] tf32-rounded
__device__ float g_wq [HH*HH];
__device__ float g_wk [HH*HH];
__device__ float g_wv [HH*HH];
__device__ float g_w1 [DOUT*HH];
__device__ float g_h  [NBS*HH];
__device__ float g_q  [NBS*HH];
__device__ float g_k  [NBS*HH];
__device__ float g_v  [NBS*HH];
__device__ float g_G  [BB*SS*SS];
__device__ float g_att[NBS*HH];

__device__ __forceinline__ unsigned f2tf(float x){
    unsigned r; asm("cvt.rna.tf32.f32 %0, %1;" : "=r"(r) : "f"(x)); return r;
}
__device__ __forceinline__ float roundtf(float x){
    return __uint_as_float(f2tf(x));
}
__device__ __forceinline__ void mma_tf32(float c[4], unsigned a0,unsigned a1,unsigned a2,unsigned a3,
                                         unsigned b0, unsigned b1){
    asm volatile("mma.sync.aligned.m16n8k8.row.col.f32.tf32.tf32.f32 "
        "{%0,%1,%2,%3},{%4,%5,%6,%7},{%8,%9},{%0,%1,%2,%3};"
        : "+f"(c[0]),"+f"(c[1]),"+f"(c[2]),"+f"(c[3])
        : "r"(a0),"r"(a1),"r"(a2),"r"(a3),"r"(b0),"r"(b1));
}
__device__ __forceinline__ void ldsm4(unsigned &r0, unsigned &r1, unsigned &r2, unsigned &r3,
                                      uint32_t addr){
    asm volatile("ldmatrix.sync.aligned.m8n8.x4.shared.b16 {%0,%1,%2,%3}, [%4];"
        : "=r"(r0),"=r"(r1),"=r"(r2),"=r"(r3) : "r"(addr));
}
__device__ __forceinline__ uint32_t smem_u32(const void* p){
    uint32_t a;
    asm("{ .reg .u64 t; cvta.to.shared.u64 t, %1; cvt.u32.u64 %0, t; }" : "=r"(a) : "l"(p));
    return a;
}
__device__ __forceinline__ void cp16(void* dst, const void* src){
    uint32_t d = smem_u32(dst);
    asm volatile("cp.async.ca.shared.global [%0], [%1], 16;" :: "r"(d), "l"(src));
}
#define CP_COMMIT() asm volatile("cp.async.commit_group;" ::: "memory")
#define CP_WAIT(n)  asm volatile("cp.async.wait_group %0;" :: "n"(n) : "memory")

// ---------------- fused prepass: round x + transpose/round weights ----------------
// blocks [0,1600): x rounding (identical body to R10's roundtf_kernel).
// blocks [1600, 2624): weight transpose tiles (identical body to R10's transpose).
__global__ __launch_bounds__(256)
void prepass_kernel(const float* __restrict__ x, float* __restrict__ xr,
                    const float* __restrict__ W0, const float* __restrict__ Wq,
                    const float* __restrict__ Wk, const float* __restrict__ Wv,
                    const float* __restrict__ W1,
                    float* __restrict__ tW0, float* __restrict__ tWq,
                    float* __restrict__ tWk, float* __restrict__ tWv,
                    float* __restrict__ tW1)
{
    __shared__ float ts[32][33];
    int bid = blockIdx.x;
    int tid = threadIdx.x;
    if (bid < 1600) {             // x: 409600 floats = 102400 float4 exactly
        int i = bid * 256 + tid;
        float4 v = ((const float4*)x)[i];
        v.x = roundtf(v.x); v.y = roundtf(v.y);
        v.z = roundtf(v.z); v.w = roundtf(v.w);
        ((float4*)xr)[i] = v;
        return;
    }
    int wb = bid - 1600;
    const float* W; float* T; int K, N, tile;
    if      (wb < 128) { W = W0; T = tW0; K = DIN; N = HH;   tile = wb; }
    else if (wb < 384) { W = Wq; T = tWq; K = HH;  N = HH;   tile = wb - 128; }
    else if (wb < 640) { W = Wk; T = tWk; K = HH;  N = HH;   tile = wb - 384; }
    else if (wb < 896) { W = Wv; T = tWv; K = HH;  N = HH;   tile = wb - 640; }
    else               { W = W1; T = tW1; K = HH;  N = DOUT; tile = wb - 896; }
    int ntiles_n = N >> 5;
    int k0 = (tile / ntiles_n) << 5;
    int n0 = (tile % ntiles_n) << 5;
    #pragma unroll
    for (int it = 0; it < 4; it++) {
        int idx = tid + it*256;
        int r = idx >> 5, c = idx & 31;
        ts[r][c] = W[(size_t)(k0 + r) * N + n0 + c];
    }
    __syncthreads();
    #pragma unroll
    for (int it = 0; it < 4; it++) {
        int idx = tid + it*256;
        int r = idx >> 5, c = idx & 31;       // r = n-local, c = k-local
        T[(size_t)(n0 + r) * K + k0 + c] = roundtf(ts[c][r]);
    }
}

// ---------------- tf32 GEMM core: 2-stage cp.async + ldmatrix, warp tile 64x32 (R10) ----------------
#define SA 36
#define SB 36
#define AS_STG (128*SA)
#define BS_STG (128*SB)
#define SMEM_GEMM ((2*AS_STG + 2*BS_STG) * 4)   // 73728 bytes

template<bool RELU, bool BIAS, bool ROUND>
__device__ __forceinline__
void gemm_core(const float* __restrict__ A, const float* __restrict__ Bt,
               const float* __restrict__ bias, float* __restrict__ C,
               int N, int K, int bm, int bn, float* smem)
{
    const int BK = 32;
    int tid = threadIdx.x, lane = tid & 31, w = tid >> 5;
    int wm = w >> 2, wn = w & 3;          // 2(M) x 4(N)
    int g = lane >> 2, t = lane & 3;
    int NK = K / BK;

    int a_row = wm*64 + (lane & 15);
    int a_col = (lane >> 4) * 4;
    int b_row = wn*32 + (lane & 7) + ((lane >> 4) << 3);
    int b_col = ((lane >> 3) & 1) * 4;

    uint32_t smem_base = smem_u32(smem);

    float acc[4][4][4] = {};

    #define ISSUE(kt) {                                                        \
        float* Asd = smem + ((kt)&1)*AS_STG;                                   \
        float* Bsd = smem + 2*AS_STG + ((kt)&1)*BS_STG;                        \
        int k0 = (kt)*BK;                                                      \
        _Pragma("unroll")                                                      \
        for (int i = 0; i < 4; i++) {                                          \
            int f = tid + i*256; int row = f>>3, c4 = f&7;                     \
            cp16(&Asd[row*SA + c4*4], &A[(size_t)(bm+row)*K + k0 + c4*4]);     \
        }                                                                      \
        _Pragma("unroll")                                                      \
        for (int i = 0; i < 4; i++) {                                          \
            int f = tid + i*256; int n = f>>3, c4 = f&7;                       \
            cp16(&Bsd[n*SB + c4*4], &Bt[(size_t)(bn+n)*K + k0 + c4*4]);        \
        }                                                                      \
        CP_COMMIT();                                                           \
    }

    ISSUE(0);
    for (int kt = 0; kt < NK; kt++) {
        if (kt + 1 < NK) { ISSUE(kt+1); CP_WAIT(1); }
        else             { CP_WAIT(0); }
        __syncthreads();
        uint32_t Asb = smem_base + ((kt&1)*AS_STG)*4;
        uint32_t Bsb = smem_base + (2*AS_STG + (kt&1)*BS_STG)*4;
        uint32_t aab = Asb + (a_row*SA + a_col)*4;
        uint32_t bab = Bsb + (b_row*SB + b_col)*4;
        #pragma unroll
        for (int ks = 0; ks < 4; ks++) {
            unsigned a[4][4], b[4][2];
            #pragma unroll
            for (int mt = 0; mt < 4; mt++)
                ldsm4(a[mt][0], a[mt][1], a[mt][2], a[mt][3],
                      aab + mt*(16*SA*4) + ks*32);
            ldsm4(b[0][0], b[0][1], b[1][0], b[1][1], bab + ks*32);
            ldsm4(b[2][0], b[2][1], b[3][0], b[3][1], bab + 16*SB*4 + ks*32);
            #pragma unroll
            for (int mt = 0; mt < 4; mt++)
                #pragma unroll
                for (int nt = 0; nt < 4; nt++)
                    mma_tf32(acc[mt][nt], a[mt][0],a[mt][1],a[mt][2],a[mt][3],
                             b[nt][0], b[nt][1]);
        }
        __syncthreads();
    }
    #undef ISSUE

    #pragma unroll
    for (int mt = 0; mt < 4; mt++) {
        int r0 = bm + wm*64 + mt*16 + g;
        #pragma unroll
        for (int nt = 0; nt < 4; nt++) {
            int col = bn + wn*32 + nt*8 + 2*t;
            float bx = 0.f, by = 0.f;
            if (BIAS) { bx = bias[col]; by = bias[col+1]; }
            float2 o0, o1;
            o0.x = acc[mt][nt][0] + bx; o0.y = acc[mt][nt][1] + by;
            o1.x = acc[mt][nt][2] + bx; o1.y = acc[mt][nt][3] + by;
            if (RELU) {
                o0.x=fmaxf(o0.x,0.f); o0.y=fmaxf(o0.y,0.f);
                o1.x=fmaxf(o1.x,0.f); o1.y=fmaxf(o1.y,0.f);
            }
            if (ROUND) {
                o0.x=roundtf(o0.x); o0.y=roundtf(o0.y);
                o1.x=roundtf(o1.x); o1.y=roundtf(o1.y);
            }
            *(float2*)&C[(size_t)r0*N + col]     = o0;
            *(float2*)&C[(size_t)(r0+8)*N + col] = o1;
        }
    }
}

template<bool RELU, bool BIAS, bool ROUND>
__global__ __launch_bounds__(256)
void tgemm_kernel(const float* __restrict__ A, const float* __restrict__ Bt,
                  const float* __restrict__ bias, float* __restrict__ C,
                  int N, int K)
{
    extern __shared__ float smem[];
    gemm_core<RELU, BIAS, ROUND>(A, Bt, bias, C, N, K,
                                 blockIdx.y * 128, blockIdx.x * 128, smem);
}

// Fused QKV: grid (12, 50).
__global__ __launch_bounds__(256)
void tgemm_qkv_kernel(const float* __restrict__ h,
                      const float* __restrict__ wq, const float* __restrict__ wk,
                      const float* __restrict__ wv,
                      float* __restrict__ q, float* __restrict__ k, float* __restrict__ v)
{
    extern __shared__ float smem[];
    int sel = blockIdx.x >> 2;
    const float* B = (sel == 0) ? wq : (sel == 1) ? wk : wv;
    float*       C = (sel == 0) ? q  : (sel == 1) ? k  : v;
    gemm_core<false, false, false>(h, B, nullptr, C, HH, HH,
                                   blockIdx.y * 128, (blockIdx.x & 3) * 128, smem);
}

// ---------------- per-batch Gram, grid (2, 64) — R10 version ----------------
__global__ __launch_bounds__(256)
void gram_kernel(const float* __restrict__ q, const float* __restrict__ kmat,
                 float* __restrict__ G)
{
    const int GSA=36, GSB=36, BK=32;
    __shared__ unsigned As[128*GSA];
    __shared__ unsigned Bs[64*GSB];
    int b = blockIdx.y;
    int n0 = blockIdx.x * 64;
    int tid = threadIdx.x, lane = tid & 31, w = tid >> 5;
    int wm = w & 3, wn = w >> 2;
    int g = lane >> 2, t = lane & 3;
    const float* qbp = q    + (size_t)b*SS*HH;
    const float* kbp = kmat + (size_t)b*SS*HH;

    float4 ar[4], br[2];
    float acc[2][4][4] = {};
    const int NK = HH / BK;

    #define LOADG(k0) {                                                        \
        _Pragma("unroll")                                                      \
        for (int i = 0; i < 4; i++) {                                          \
            int f = tid + i*256; int row = f>>3, c4 = (f&7)*4;                 \
            int sr = row < SS ? row : SS-1;                                    \
            ar[i] = *(const float4*)&qbp[(size_t)sr*HH + (k0) + c4];           \
        }                                                                      \
        _Pragma("unroll")                                                      \
        for (int i = 0; i < 2; i++) {                                          \
            int f = tid + i*256; int u = f>>3, c4 = (f&7)*4;                   \
            int su = (n0+u) < SS ? (n0+u) : SS-1;                              \
            br[i] = *(const float4*)&kbp[(size_t)su*HH + (k0) + c4];           \
        }                                                                      \
    }
    #define STORES() {                                                         \
        _Pragma("unroll")                                                      \
        for (int i = 0; i < 4; i++) {                                          \
            int f = tid + i*256; int row = f>>3, c4 = (f&7)*4;                 \
            int base = (c4>>3)*8 + (((c4&7)==4) ? 1 : 0);                      \
            unsigned* d = &As[row*GSA + base];                                 \
            d[0]=f2tf(ar[i].x); d[2]=f2tf(ar[i].y);                            \
            d[4]=f2tf(ar[i].z); d[6]=f2tf(ar[i].w);                            \
        }                                                                      \
        _Pragma("unroll")                                                      \
        for (int i = 0; i < 2; i++) {                                          \
            int f = tid + i*256; int u = f>>3, c4 = (f&7)*4;                   \
            int base = (c4>>3)*8 + (((c4&7)==4) ? 1 : 0);                      \
            unsigned* d = &Bs[u*GSB + base];                                   \
            d[0]=f2tf(br[i].x); d[2]=f2tf(br[i].y);                            \
            d[4]=f2tf(br[i].z); d[6]=f2tf(br[i].w);                            \
        }                                                                      \
    }

    LOADG(0); STORES(); __syncthreads();

    for (int kt = 0; kt < NK; kt++) {
        if (kt + 1 < NK) LOADG((kt+1)*BK);
        #pragma unroll
        for (int ks = 0; ks < 4; ks++) {
            unsigned a[2][4], bfr[4][2];
            #pragma unroll
            for (int mt = 0; mt < 2; mt++) {
                int r = wm*32 + mt*16 + g;
                uint2 lo = *(const uint2*)&As[r*GSA + ks*8 + 2*t];
                uint2 hi = *(const uint2*)&As[(r+8)*GSA + ks*8 + 2*t];
                a[mt][0]=lo.x; a[mt][1]=hi.x; a[mt][2]=lo.y; a[mt][3]=hi.y;
            }
            #pragma unroll
            for (int nt = 0; nt < 4; nt++) {
                int n = wn*32 + nt*8 + g;
                uint2 bb = *(const uint2*)&Bs[n*GSB + ks*8 + 2*t];
                bfr[nt][0]=bb.x; bfr[nt][1]=bb.y;
            }
            #pragma unroll
            for (int mt = 0; mt < 2; mt++)
                #pragma unroll
                for (int nt = 0; nt < 4; nt++)
                    mma_tf32(acc[mt][nt], a[mt][0],a[mt][1],a[mt][2],a[mt][3],
                             bfr[nt][0], bfr[nt][1]);
        }
        __syncthreads();
        if (kt + 1 < NK) { STORES(); __syncthreads(); }
    }
    #undef LOADG
    #undef STORES

    const float invs = 0.044194173824159216f;  // 1/sqrt(512)
    float* Gb = G + (size_t)b*SS*SS;
    #pragma unroll
    for (int mt = 0; mt < 2; mt++) {
        int r0 = wm*32 + mt*16 + g;
        #pragma unroll
        for (int nt = 0; nt < 4; nt++) {
            int col = n0 + wn*32 + nt*8 + 2*t;
            if (col + 1 < SS) {
                if (r0 < SS) {
                    Gb[r0*SS + col]     = acc[mt][nt][0]*invs;
                    Gb[r0*SS + col + 1] = acc[mt][nt][1]*invs;
                }
                if (r0 + 8 < SS) {
                    Gb[(r0+8)*SS + col]     = acc[mt][nt][2]*invs;
                    Gb[(r0+8)*SS + col + 1] = acc[mt][nt][3]*invs;
                }
            } else if (col < SS) {
                if (r0 < SS)     Gb[r0*SS + col]     = acc[mt][nt][0]*invs;
                if (r0 + 8 < SS) Gb[(r0+8)*SS + col] = acc[mt][nt][2]*invs;
            }
        }
    }
}

// ---------------- softmax + beta + weighted V (STILE=4, R10 version) ----------------
__global__ __launch_bounds__(256)
void attn_kernel(const float* __restrict__ G, const float* __restrict__ v,
                 float* __restrict__ alpha_out, float* __restrict__ att)
{
    int blk = blockIdx.x;
    int b  = blk / (SS / STILE);
    int s0 = (blk % (SS / STILE)) * STILE;
    __shared__ float dmat[STILE][WIN * WIN];
    __shared__ float beta[STILE][WIN];
    const float* Gb = G + (size_t)b*SS*SS;
    int tid = threadIdx.x;

    for (int idx = tid; idx < STILE*WIN*WIN; idx += 256) {
        int si = idx / (WIN*WIN), r = idx % (WIN*WIN);
        int w_ = r / WIN, u = r % WIN;
        int s = s0 + si;
        int p  = s + WR - w_;
        int pu = s + WR - u;
        float val = 0.f;
        if (p >= 0 && p < SS && pu >= 0 && pu < SS)
            val = Gb[p*SS + pu];
        dmat[si][r] = val;
    }
    __syncthreads();

    int warp = tid >> 5, lane = tid & 31;
    for (int rr = warp; rr < STILE*WIN; rr += 8) {
        int si = rr / WIN, r = rr % WIN;
        float* row = &dmat[si][r*WIN];
        float x0 = row[lane];
        float x1 = (lane == 0) ? row[32] : -1e30f;
        float m = fmaxf(x0, x1);
#pragma unroll
        for (int o = 16; o; o >>= 1)
            m = fmaxf(m, __shfl_xor_sync(0xffffffffu, m, o));
        float e0 = __expf(x0 - m);
        float e1 = (lane == 0) ? __expf(x1 - m) : 0.f;
        float ssum = e0 + e1;
#pragma unroll
        for (int o = 16; o; o >>= 1)
            ssum += __shfl_xor_sync(0xffffffffu, ssum, o);
        float rinv = __frcp_rn(ssum);
        e0 *= rinv; e1 *= rinv;
        row[lane] = e0;
        if (lane == 0) row[32] = e1;
        float* ao = alpha_out + (size_t)(b*SS + s0 + si)*(WIN*WIN) + r*WIN;
        ao[lane] = e0;
        if (lane == 0) ao[32] = e1;
    }
    __syncthreads();

    for (int idx = tid; idx < STILE*WIN; idx += 256) {
        int si = idx / WIN, u = idx % WIN;
        float acc = 0.f;
        for (int r = 0; r < WIN; r++) acc += dmat[si][r*WIN + u];
        beta[si][u] = acc;
    }
    __syncthreads();

    int h2 = tid * 2;
    float2 acc[STILE];
#pragma unroll
    for (int si = 0; si < STILE; si++) { acc[si].x = 0.f; acc[si].y = 0.f; }

#pragma unroll
    for (int j = 0; j < STILE - 1 + 2*WR + 1; j++) {   // 36 window positions
        int p = s0 - WR + j;
        if (p >= 0 && p < SS) {
            float2 vr = *(const float2*)&v[(size_t)(b*SS + p)*HH + h2];
#pragma unroll
            for (int si = 0; si < STILE; si++) {
                int u = si + 2*WR - j;
                if (u >= 0 && u < WIN) {
                    float bu = beta[si][u];
                    acc[si].x = fmaf(bu, vr.x, acc[si].x);
                    acc[si].y = fmaf(bu, vr.y, acc[si].y);
                }
            }
        }
    }
#pragma unroll
    for (int si = 0; si < STILE; si++) {
        float2 o;
        o.x = roundtf(acc[si].x);
        o.y = roundtf(acc[si].y);
        *(float2*)&att[(size_t)(b*SS + s0 + si)*HH + h2] = o;
    }
}

// ---------------- launch ----------------
extern "C" void kernel_launch(void* const* d_in, const int* in_sizes, int n_in,
                              void* d_out, int out_size)
{
    const float* x  = (const float*)d_in[0];
    const float* W0 = (const float*)d_in[1];
    const float* b0 = (const float*)d_in[2];
    const float* Wq = (const float*)d_in[3];
    const float* Wk = (const float*)d_in[4];
    const float* Wv = (const float*)d_in[5];
    const float* W1 = (const float*)d_in[6];
    const float* b1 = (const float*)d_in[7];
    float* out = (float*)d_out;
    float* y_out     = out;
    float* alpha_out = out + (size_t)NBS * DOUT;

    float *xr,*w0t,*wqt,*wkt,*wvt,*w1t,*h,*q,*k,*v,*G,*att;
    cudaGetSymbolAddress((void**)&xr,  g_x);
    cudaGetSymbolAddress((void**)&w0t, g_w0);
    cudaGetSymbolAddress((void**)&wqt, g_wq);
    cudaGetSymbolAddress((void**)&wkt, g_wk);
    cudaGetSymbolAddress((void**)&wvt, g_wv);
    cudaGetSymbolAddress((void**)&w1t, g_w1);
    cudaGetSymbolAddress((void**)&h,   g_h);
    cudaGetSymbolAddress((void**)&q,   g_q);
    cudaGetSymbolAddress((void**)&k,   g_k);
    cudaGetSymbolAddress((void**)&v,   g_v);
    cudaGetSymbolAddress((void**)&G,   g_G);
    cudaGetSymbolAddress((void**)&att, g_att);

    cudaFuncSetAttribute(tgemm_kernel<true, true, true >, cudaFuncAttributeMaxDynamicSharedMemorySize, SMEM_GEMM);
    cudaFuncSetAttribute(tgemm_kernel<true, true, false>, cudaFuncAttributeMaxDynamicSharedMemorySize, SMEM_GEMM);
    cudaFuncSetAttribute(tgemm_qkv_kernel, cudaFuncAttributeMaxDynamicSharedMemorySize, SMEM_GEMM);

    // fused prepass: x round (1600 blocks) + weight transpose (1024 blocks)
    prepass_kernel<<<2624, 256>>>(x, xr, W0, Wq, Wk, Wv, W1,
                                  w0t, wqt, wkt, wvt, w1t);

    // h = relu(x@W0 + b0), tf32-rounded
    tgemm_kernel<true, true, true><<<dim3(HH/128, NBS/128), 256, SMEM_GEMM>>>(
        xr, w0t, b0, h, HH, DIN);
    // fused q,k,v
    tgemm_qkv_kernel<<<dim3(12, NBS/128), 256, SMEM_GEMM>>>(h, wqt, wkt, wvt, q, k, v);
    // Gram (R10 version): grid (2, 64)
    gram_kernel<<<dim3(2, BB), 256>>>(q, k, G);
    // softmax + alpha + weighted V (STILE=4, R10 version)
    attn_kernel<<<NBS/STILE, 256>>>(G, v, alpha_out, att);
    // y = relu(att@W1 + b1)
    tgemm_kernel<true, true, false><<<dim3(DOUT/128, NBS/128), 256, SMEM_GEMM>>>(
        att, w1t, b1, y_out, DOUT, HH);
}

// round 17
// speedup vs baseline: 1.1144x; 1.0351x over previous
#include <cuda_runtime.h>
#include <stdint.h>
#include <math.h>

#define BB 64
#define SS 100
#define DIN 256
#define HH 512
#define DOUT 256
#define WR 16
#define WIN 33
#define NBS (BB*SS)
#define STILE 4

// ---------------- scratch ----------------
__device__ float g_x  [NBS*DIN];   // x tf32-rounded
__device__ float g_w0 [HH*DIN];    // W0^T [N,K] tf32-rounded
__device__ float g_wq [HH*HH];
__device__ float g_wk [HH*HH];
__device__ float g_wv [HH*HH];
__device__ float g_w1 [DOUT*HH];
__device__ float g_h  [NBS*HH];
__device__ float g_q  [NBS*HH];    // tf32-rounded by QKV epilogue
__device__ float g_k  [NBS*HH];    // tf32-rounded by QKV epilogue
__device__ float g_v  [NBS*HH];    // raw fp32
__device__ float g_G  [BB*SS*SS];
__device__ float g_att[NBS*HH];

__device__ __forceinline__ unsigned f2tf(float x){
    unsigned r; asm("cvt.rna.tf32.f32 %0, %1;" : "=r"(r) : "f"(x)); return r;
}
__device__ __forceinline__ float roundtf(float x){
    return __uint_as_float(f2tf(x));
}
__device__ __forceinline__ void mma_tf32(float c[4], unsigned a0,unsigned a1,unsigned a2,unsigned a3,
                                         unsigned b0, unsigned b1){
    asm volatile("mma.sync.aligned.m16n8k8.row.col.f32.tf32.tf32.f32 "
        "{%0,%1,%2,%3},{%4,%5,%6,%7},{%8,%9},{%0,%1,%2,%3};"
        : "+f"(c[0]),"+f"(c[1]),"+f"(c[2]),"+f"(c[3])
        : "r"(a0),"r"(a1),"r"(a2),"r"(a3),"r"(b0),"r"(b1));
}
__device__ __forceinline__ void ldsm4(unsigned &r0, unsigned &r1, unsigned &r2, unsigned &r3,
                                      uint32_t addr){
    asm volatile("ldmatrix.sync.aligned.m8n8.x4.shared.b16 {%0,%1,%2,%3}, [%4];"
        : "=r"(r0),"=r"(r1),"=r"(r2),"=r"(r3) : "r"(addr));
}
__device__ __forceinline__ uint32_t smem_u32(const void* p){
    uint32_t a;
    asm("{ .reg .u64 t; cvta.to.shared.u64 t, %1; cvt.u32.u64 %0, t; }" : "=r"(a) : "l"(p));
    return a;
}
__device__ __forceinline__ void cp16(void* dst, const void* src){
    uint32_t d = smem_u32(dst);
    asm volatile("cp.async.ca.shared.global [%0], [%1], 16;" :: "r"(d), "l"(src));
}
#define CP_COMMIT() asm volatile("cp.async.commit_group;" ::: "memory")
#define CP_WAIT(n)  asm volatile("cp.async.wait_group %0;" :: "n"(n) : "memory")

// ---------------- fused prepass: round x + transpose/round weights ----------------
__global__ __launch_bounds__(256)
void prepass_kernel(const float* __restrict__ x, float* __restrict__ xr,
                    const float* __restrict__ W0, const float* __restrict__ Wq,
                    const float* __restrict__ Wk, const float* __restrict__ Wv,
                    const float* __restrict__ W1,
                    float* __restrict__ tW0, float* __restrict__ tWq,
                    float* __restrict__ tWk, float* __restrict__ tWv,
                    float* __restrict__ tW1)
{
    __shared__ float ts[32][33];
    int bid = blockIdx.x;
    int tid = threadIdx.x;
    if (bid < 1600) {             // x: 409600 floats = 102400 float4 exactly
        int i = bid * 256 + tid;
        float4 v = ((const float4*)x)[i];
        v.x = roundtf(v.x); v.y = roundtf(v.y);
        v.z = roundtf(v.z); v.w = roundtf(v.w);
        ((float4*)xr)[i] = v;
        return;
    }
    int wb = bid - 1600;
    const float* W; float* T; int K, N, tile;
    if      (wb < 128) { W = W0; T = tW0; K = DIN; N = HH;   tile = wb; }
    else if (wb < 384) { W = Wq; T = tWq; K = HH;  N = HH;   tile = wb - 128; }
    else if (wb < 640) { W = Wk; T = tWk; K = HH;  N = HH;   tile = wb - 384; }
    else if (wb < 896) { W = Wv; T = tWv; K = HH;  N = HH;   tile = wb - 640; }
    else               { W = W1; T = tW1; K = HH;  N = DOUT; tile = wb - 896; }
    int ntiles_n = N >> 5;
    int k0 = (tile / ntiles_n) << 5;
    int n0 = (tile % ntiles_n) << 5;
    #pragma unroll
    for (int it = 0; it < 4; it++) {
        int idx = tid + it*256;
        int r = idx >> 5, c = idx & 31;
        ts[r][c] = W[(size_t)(k0 + r) * N + n0 + c];
    }
    __syncthreads();
    #pragma unroll
    for (int it = 0; it < 4; it++) {
        int idx = tid + it*256;
        int r = idx >> 5, c = idx & 31;
        T[(size_t)(n0 + r) * K + k0 + c] = roundtf(ts[c][r]);
    }
}

// ---------------- tf32 GEMM core: 2-stage cp.async + ldmatrix, warp tile 64x32 ----------------
#define SA 36
#define SB 36
#define AS_STG (128*SA)
#define BS_STG (128*SB)
#define SMEM_GEMM ((2*AS_STG + 2*BS_STG) * 4)   // 73728 bytes

template<bool RELU, bool BIAS, bool ROUND>
__device__ __forceinline__
void gemm_core(const float* __restrict__ A, const float* __restrict__ Bt,
               const float* __restrict__ bias, float* __restrict__ C,
               int N, int K, int bm, int bn, float* smem, bool rnd = false)
{
    const int BK = 32;
    int tid = threadIdx.x, lane = tid & 31, w = tid >> 5;
    int wm = w >> 2, wn = w & 3;          // 2(M) x 4(N)
    int g = lane >> 2, t = lane & 3;
    int NK = K / BK;

    int a_row = wm*64 + (lane & 15);
    int a_col = (lane >> 4) * 4;
    int b_row = wn*32 + (lane & 7) + ((lane >> 4) << 3);
    int b_col = ((lane >> 3) & 1) * 4;

    uint32_t smem_base = smem_u32(smem);

    float acc[4][4][4] = {};

    #define ISSUE(kt) {                                                        \
        float* Asd = smem + ((kt)&1)*AS_STG;                                   \
        float* Bsd = smem + 2*AS_STG + ((kt)&1)*BS_STG;                        \
        int k0 = (kt)*BK;                                                      \
        _Pragma("unroll")                                                      \
        for (int i = 0; i < 4; i++) {                                          \
            int f = tid + i*256; int row = f>>3, c4 = f&7;                     \
            cp16(&Asd[row*SA + c4*4], &A[(size_t)(bm+row)*K + k0 + c4*4]);     \
        }                                                                      \
        _Pragma("unroll")                                                      \
        for (int i = 0; i < 4; i++) {                                          \
            int f = tid + i*256; int n = f>>3, c4 = f&7;                       \
            cp16(&Bsd[n*SB + c4*4], &Bt[(size_t)(bn+n)*K + k0 + c4*4]);        \
        }                                                                      \
        CP_COMMIT();                                                           \
    }

    ISSUE(0);
    for (int kt = 0; kt < NK; kt++) {
        if (kt + 1 < NK) { ISSUE(kt+1); CP_WAIT(1); }
        else             { CP_WAIT(0); }
        __syncthreads();
        uint32_t Asb = smem_base + ((kt&1)*AS_STG)*4;
        uint32_t Bsb = smem_base + (2*AS_STG + (kt&1)*BS_STG)*4;
        uint32_t aab = Asb + (a_row*SA + a_col)*4;
        uint32_t bab = Bsb + (b_row*SB + b_col)*4;
        #pragma unroll
        for (int ks = 0; ks < 4; ks++) {
            unsigned a[4][4], b[4][2];
            #pragma unroll
            for (int mt = 0; mt < 4; mt++)
                ldsm4(a[mt][0], a[mt][1], a[mt][2], a[mt][3],
                      aab + mt*(16*SA*4) + ks*32);
            ldsm4(b[0][0], b[0][1], b[1][0], b[1][1], bab + ks*32);
            ldsm4(b[2][0], b[2][1], b[3][0], b[3][1], bab + 16*SB*4 + ks*32);
            #pragma unroll
            for (int mt = 0; mt < 4; mt++)
                #pragma unroll
                for (int nt = 0; nt < 4; nt++)
                    mma_tf32(acc[mt][nt], a[mt][0],a[mt][1],a[mt][2],a[mt][3],
                             b[nt][0], b[nt][1]);
        }
        __syncthreads();
    }
    #undef ISSUE

    #pragma unroll
    for (int mt = 0; mt < 4; mt++) {
        int r0 = bm + wm*64 + mt*16 + g;
        #pragma unroll
        for (int nt = 0; nt < 4; nt++) {
            int col = bn + wn*32 + nt*8 + 2*t;
            float bx = 0.f, by = 0.f;
            if (BIAS) { bx = bias[col]; by = bias[col+1]; }
            float2 o0, o1;
            o0.x = acc[mt][nt][0] + bx; o0.y = acc[mt][nt][1] + by;
            o1.x = acc[mt][nt][2] + bx; o1.y = acc[mt][nt][3] + by;
            if (RELU) {
                o0.x=fmaxf(o0.x,0.f); o0.y=fmaxf(o0.y,0.f);
                o1.x=fmaxf(o1.x,0.f); o1.y=fmaxf(o1.y,0.f);
            }
            if (ROUND || rnd) {
                o0.x=roundtf(o0.x); o0.y=roundtf(o0.y);
                o1.x=roundtf(o1.x); o1.y=roundtf(o1.y);
            }
            *(float2*)&C[(size_t)r0*N + col]     = o0;
            *(float2*)&C[(size_t)(r0+8)*N + col] = o1;
        }
    }
}

template<bool RELU, bool BIAS, bool ROUND>
__global__ __launch_bounds__(256)
void tgemm_kernel(const float* __restrict__ A, const float* __restrict__ Bt,
                  const float* __restrict__ bias, float* __restrict__ C,
                  int N, int K)
{
    extern __shared__ float smem[];
    gemm_core<RELU, BIAS, ROUND>(A, Bt, bias, C, N, K,
                                 blockIdx.y * 128, blockIdx.x * 128, smem);
}

// Fused QKV: grid (12, 50). q,k written tf32-rounded (feeds gram); v raw fp32.
__global__ __launch_bounds__(256)
void tgemm_qkv_kernel(const float* __restrict__ h,
                      const float* __restrict__ wq, const float* __restrict__ wk,
                      const float* __restrict__ wv,
                      float* __restrict__ q, float* __restrict__ k, float* __restrict__ v)
{
    extern __shared__ float smem[];
    int sel = blockIdx.x >> 2;
    const float* B = (sel == 0) ? wq : (sel == 1) ? wk : wv;
    float*       C = (sel == 0) ? q  : (sel == 1) ? k  : v;
    gemm_core<false, false, false>(h, B, nullptr, C, HH, HH,
                                   blockIdx.y * 128, (blockIdx.x & 3) * 128, smem,
                                   sel != 2);
}

// ---------------- gram: cp.async + ldmatrix, grid (2, 64), tile A128x32 B64x32 ----------------
// q,k already tf32-rounded. Row-clamped cp.async sources; masked scaled store.
#define GAS (128*SA)
#define GBS (64*SB)
#define SMEM_GRAM ((2*GAS + 2*GBS) * 4)   // 55296 bytes

__global__ __launch_bounds__(256)
void gram_kernel(const float* __restrict__ q, const float* __restrict__ kmat,
                 float* __restrict__ G)
{
    extern __shared__ float smem[];
    const int BK = 32;
    int b = blockIdx.y;
    int n0 = blockIdx.x * 64;
    int tid = threadIdx.x, lane = tid & 31, w = tid >> 5;
    int wm = w & 3, wn = w >> 2;          // 4(M) x 2(N), warp tile 32x32
    int g = lane >> 2, t = lane & 3;
    const float* qbp = q    + (size_t)b*SS*HH;
    const float* kbp = kmat + (size_t)b*SS*HH;
    const int NK = HH / BK;

    int a_row = wm*32 + (lane & 15);                      // + mt*16
    int a_col = (lane >> 4) * 4;
    int b_row = wn*32 + (lane & 7) + ((lane >> 4) << 3);  // + pair*16
    int b_col = ((lane >> 3) & 1) * 4;

    uint32_t smem_base = smem_u32(smem);

    float acc[2][4][4] = {};

    #define GISSUE(kt) {                                                       \
        float* Asd = smem + ((kt)&1)*GAS;                                      \
        float* Bsd = smem + 2*GAS + ((kt)&1)*GBS;                              \
        int k0 = (kt)*BK;                                                      \
        _Pragma("unroll")                                                      \
        for (int i = 0; i < 4; i++) {                                          \
            int f = tid + i*256; int row = f>>3, c4 = f&7;                     \
            int sr = row < SS ? row : SS-1;                                    \
            cp16(&Asd[row*SA + c4*4], &qbp[(size_t)sr*HH + k0 + c4*4]);        \
        }                                                                      \
        _Pragma("unroll")                                                      \
        for (int i = 0; i < 2; i++) {                                          \
            int f = tid + i*256; int u = f>>3, c4 = f&7;                       \
            int su = (n0+u) < SS ? (n0+u) : SS-1;                              \
            cp16(&Bsd[u*SB + c4*4], &kbp[(size_t)su*HH + k0 + c4*4]);          \
        }                                                                      \
        CP_COMMIT();                                                           \
    }

    GISSUE(0);
    for (int kt = 0; kt < NK; kt++) {
        if (kt + 1 < NK) { GISSUE(kt+1); CP_WAIT(1); }
        else             { CP_WAIT(0); }
        __syncthreads();
        uint32_t Asb = smem_base + ((kt&1)*GAS)*4;
        uint32_t Bsb = smem_base + (2*GAS + (kt&1)*GBS)*4;
        uint32_t aab = Asb + (a_row*SA + a_col)*4;
        uint32_t bab = Bsb + (b_row*SB + b_col)*4;
        #pragma unroll
        for (int ks = 0; ks < 4; ks++) {
            unsigned a[2][4], bfr[4][2];
            ldsm4(a[0][0], a[0][1], a[0][2], a[0][3], aab + ks*32);
            ldsm4(a[1][0], a[1][1], a[1][2], a[1][3], aab + 16*SA*4 + ks*32);
            ldsm4(bfr[0][0], bfr[0][1], bfr[1][0], bfr[1][1], bab + ks*32);
            ldsm4(bfr[2][0], bfr[2][1], bfr[3][0], bfr[3][1], bab + 16*SB*4 + ks*32);
            #pragma unroll
            for (int mt = 0; mt < 2; mt++)
                #pragma unroll
                for (int nt = 0; nt < 4; nt++)
                    mma_tf32(acc[mt][nt], a[mt][0],a[mt][1],a[mt][2],a[mt][3],
                             bfr[nt][0], bfr[nt][1]);
        }
        __syncthreads();
    }
    #undef GISSUE

    const float invs = 0.044194173824159216f;  // 1/sqrt(512)
    float* Gb = G + (size_t)b*SS*SS;
    #pragma unroll
    for (int mt = 0; mt < 2; mt++) {
        int r0 = wm*32 + mt*16 + g;
        #pragma unroll
        for (int nt = 0; nt < 4; nt++) {
            int col = n0 + wn*32 + nt*8 + 2*t;
            if (col + 1 < SS) {
                if (r0 < SS) {
                    Gb[r0*SS + col]     = acc[mt][nt][0]*invs;
                    Gb[r0*SS + col + 1] = acc[mt][nt][1]*invs;
                }
                if (r0 + 8 < SS) {
                    Gb[(r0+8)*SS + col]     = acc[mt][nt][2]*invs;
                    Gb[(r0+8)*SS + col + 1] = acc[mt][nt][3]*invs;
                }
            } else if (col < SS) {
                if (r0 < SS)     Gb[r0*SS + col]     = acc[mt][nt][0]*invs;
                if (r0 + 8 < SS) Gb[(r0+8)*SS + col] = acc[mt][nt][2]*invs;
            }
        }
    }
}

// ---------------- softmax + beta + weighted V (STILE=4) ----------------
__global__ __launch_bounds__(256)
void attn_kernel(const float* __restrict__ G, const float* __restrict__ v,
                 float* __restrict__ alpha_out, float* __restrict__ att)
{
    int blk = blockIdx.x;
    int b  = blk / (SS / STILE);
    int s0 = (blk % (SS / STILE)) * STILE;
    __shared__ float dmat[STILE][WIN * WIN];
    __shared__ float beta[STILE][WIN];
    const float* Gb = G + (size_t)b*SS*SS;
    int tid = threadIdx.x;

    for (int idx = tid; idx < STILE*WIN*WIN; idx += 256) {
        int si = idx / (WIN*WIN), r = idx % (WIN*WIN);
        int w_ = r / WIN, u = r % WIN;
        int s = s0 + si;
        int p  = s + WR - w_;
        int pu = s + WR - u;
        float val = 0.f;
        if (p >= 0 && p < SS && pu >= 0 && pu < SS)
            val = Gb[p*SS + pu];
        dmat[si][r] = val;
    }
    __syncthreads();

    int warp = tid >> 5, lane = tid & 31;
    for (int rr = warp; rr < STILE*WIN; rr += 8) {
        int si = rr / WIN, r = rr % WIN;
        float* row = &dmat[si][r*WIN];
        float x0 = row[lane];
        float x1 = (lane == 0) ? row[32] : -1e30f;
        float m = fmaxf(x0, x1);
#pragma unroll
        for (int o = 16; o; o >>= 1)
            m = fmaxf(m, __shfl_xor_sync(0xffffffffu, m, o));
        float e0 = __expf(x0 - m);
        float e1 = (lane == 0) ? __expf(x1 - m) : 0.f;
        float ssum = e0 + e1;
#pragma unroll
        for (int o = 16; o; o >>= 1)
            ssum += __shfl_xor_sync(0xffffffffu, ssum, o);
        float rinv = __frcp_rn(ssum);
        e0 *= rinv; e1 *= rinv;
        row[lane] = e0;
        if (lane == 0) row[32] = e1;
        float* ao = alpha_out + (size_t)(b*SS + s0 + si)*(WIN*WIN) + r*WIN;
        ao[lane] = e0;
        if (lane == 0) ao[32] = e1;
    }
    __syncthreads();

    for (int idx = tid; idx < STILE*WIN; idx += 256) {
        int si = idx / WIN, u = idx % WIN;
        float acc = 0.f;
        for (int r = 0; r < WIN; r++) acc += dmat[si][r*WIN + u];
        beta[si][u] = acc;
    }
    __syncthreads();

    int h2 = tid * 2;
    float2 acc[STILE];
#pragma unroll
    for (int si = 0; si < STILE; si++) { acc[si].x = 0.f; acc[si].y = 0.f; }

#pragma unroll
    for (int j = 0; j < STILE - 1 + 2*WR + 1; j++) {   // 36 window positions
        int p = s0 - WR + j;
        if (p >= 0 && p < SS) {
            float2 vr = *(const float2*)&v[(size_t)(b*SS + p)*HH + h2];
#pragma unroll
            for (int si = 0; si < STILE; si++) {
                int u = si + 2*WR - j;
                if (u >= 0 && u < WIN) {
                    float bu = beta[si][u];
                    acc[si].x = fmaf(bu, vr.x, acc[si].x);
                    acc[si].y = fmaf(bu, vr.y, acc[si].y);
                }
            }
        }
    }
#pragma unroll
    for (int si = 0; si < STILE; si++) {
        float2 o;
        o.x = roundtf(acc[si].x);
        o.y = roundtf(acc[si].y);
        *(float2*)&att[(size_t)(b*SS + s0 + si)*HH + h2] = o;
    }
}

// ---------------- launch ----------------
extern "C" void kernel_launch(void* const* d_in, const int* in_sizes, int n_in,
                              void* d_out, int out_size)
{
    const float* x  = (const float*)d_in[0];
    const float* W0 = (const float*)d_in[1];
    const float* b0 = (const float*)d_in[2];
    const float* Wq = (const float*)d_in[3];
    const float* Wk = (const float*)d_in[4];
    const float* Wv = (const float*)d_in[5];
    const float* W1 = (const float*)d_in[6];
    const float* b1 = (const float*)d_in[7];
    float* out = (float*)d_out;
    float* y_out     = out;
    float* alpha_out = out + (size_t)NBS * DOUT;

    float *xr,*w0t,*wqt,*wkt,*wvt,*w1t,*h,*q,*k,*v,*G,*att;
    cudaGetSymbolAddress((void**)&xr,  g_x);
    cudaGetSymbolAddress((void**)&w0t, g_w0);
    cudaGetSymbolAddress((void**)&wqt, g_wq);
    cudaGetSymbolAddress((void**)&wkt, g_wk);
    cudaGetSymbolAddress((void**)&wvt, g_wv);
    cudaGetSymbolAddress((void**)&w1t, g_w1);
    cudaGetSymbolAddress((void**)&h,   g_h);
    cudaGetSymbolAddress((void**)&q,   g_q);
    cudaGetSymbolAddress((void**)&k,   g_k);
    cudaGetSymbolAddress((void**)&v,   g_v);
    cudaGetSymbolAddress((void**)&G,   g_G);
    cudaGetSymbolAddress((void**)&att, g_att);

    cudaFuncSetAttribute(tgemm_kernel<true, true, true >, cudaFuncAttributeMaxDynamicSharedMemorySize, SMEM_GEMM);
    cudaFuncSetAttribute(tgemm_kernel<true, true, false>, cudaFuncAttributeMaxDynamicSharedMemorySize, SMEM_GEMM);
    cudaFuncSetAttribute(tgemm_qkv_kernel, cudaFuncAttributeMaxDynamicSharedMemorySize, SMEM_GEMM);
    cudaFuncSetAttribute(gram_kernel,      cudaFuncAttributeMaxDynamicSharedMemorySize, SMEM_GRAM);

    // fused prepass: x round (1600 blocks) + weight transpose (1024 blocks)
    prepass_kernel<<<2624, 256>>>(x, xr, W0, Wq, Wk, Wv, W1,
                                  w0t, wqt, wkt, wvt, w1t);

    // h = relu(x@W0 + b0), tf32-rounded
    tgemm_kernel<true, true, true><<<dim3(HH/128, NBS/128), 256, SMEM_GEMM>>>(
        xr, w0t, b0, h, HH, DIN);
    // fused q,k,v (q,k tf32-rounded; v raw)
    tgemm_qkv_kernel<<<dim3(12, NBS/128), 256, SMEM_GEMM>>>(h, wqt, wkt, wvt, q, k, v);
    // gram: cp.async + ldmatrix, grid (2, 64)
    gram_kernel<<<dim3(2, BB), 256, SMEM_GRAM>>>(q, k, G);
    // softmax + alpha + weighted V
    attn_kernel<<<NBS/STILE, 256>>>(G, v, alpha_out, att);
    // y = relu(att@W1 + b1)
    tgemm_kernel<true, true, false><<<dim3(DOUT/128, NBS/128), 256, SMEM_GEMM>>>(
        att, w1t, b1, y_out, DOUT, HH);
}